// round 1
// baseline (speedup 1.0000x reference)
#include <cuda_runtime.h>
#include <cstdint>

// ---------------------------------------------------------------------------
// TernaryLinear: y = (rowwise-int8-quant(x) @ w_t^T) * act_scale * w_scale + bias
//   x:    [8192, 4096] f32 (4*2048 tokens)
//   w_t:  [4096, 4096] f32 in {-1,0,+1}
//   w_scale: scalar f32
//   bias: [4096] f32
//   out:  [8192, 4096] f32
//
// Pipeline:
//   K1: per-row absmax int8 quantization of x  -> g_xq, g_ascale
//   K2: f32 -> int8 convert of w_t             -> g_wq
//   K3: int8 IMMA GEMM (m16n8k32), 128x128x64 tiles, cp.async double buffer,
//       fused dequant + bias epilogue.
// ---------------------------------------------------------------------------

#define T_TOKENS 8192
#define KDIM     4096
#define ODIM     4096

#define BM 128
#define BN 128
#define BK 64
#define ASTRIDE 80   // padded smem row stride in bytes (conflict-free frag loads)

// Scratch (allocation-free per harness rules)
__device__ int8_t g_xq[(size_t)T_TOKENS * KDIM];
__device__ int8_t g_wq[(size_t)ODIM * KDIM];
__device__ float  g_ascale[T_TOKENS];

// ---------------------------------------------------------------------------
// K1: quantize activations. One block per token row.
// ---------------------------------------------------------------------------
__global__ __launch_bounds__(256) void quant_x_kernel(const float* __restrict__ x) {
    const int row = blockIdx.x;
    const float4* xr = reinterpret_cast<const float4*>(x + (size_t)row * KDIM);

    float m = 0.0f;
    #pragma unroll 4
    for (int i = threadIdx.x; i < KDIM / 4; i += 256) {
        float4 v = xr[i];
        m = fmaxf(m, fmaxf(fmaxf(fabsf(v.x), fabsf(v.y)),
                           fmaxf(fabsf(v.z), fabsf(v.w))));
    }
    #pragma unroll
    for (int o = 16; o; o >>= 1) m = fmaxf(m, __shfl_xor_sync(0xffffffffu, m, o));

    __shared__ float warpmax[8];
    __shared__ float s_inv;
    const int wid = threadIdx.x >> 5, lane = threadIdx.x & 31;
    if (lane == 0) warpmax[wid] = m;
    __syncthreads();
    if (threadIdx.x == 0) {
        float mm = warpmax[0];
        #pragma unroll
        for (int i = 1; i < 8; i++) mm = fmaxf(mm, warpmax[i]);
        float sc = fmaxf(mm, 1e-10f) / 127.0f;   // act_scale = max(absmax, EPS)/127
        g_ascale[row] = sc;
        s_inv = 1.0f / sc;
    }
    __syncthreads();
    const float inv = s_inv;

    char4* outq = reinterpret_cast<char4*>(g_xq + (size_t)row * KDIM);
    for (int i = threadIdx.x; i < KDIM / 4; i += 256) {
        float4 v = xr[i];   // L2 hit on re-read
        char4 c;
        c.x = (signed char)(int)fminf(fmaxf(rintf(v.x * inv), -127.0f), 127.0f);
        c.y = (signed char)(int)fminf(fmaxf(rintf(v.y * inv), -127.0f), 127.0f);
        c.z = (signed char)(int)fminf(fmaxf(rintf(v.z * inv), -127.0f), 127.0f);
        c.w = (signed char)(int)fminf(fmaxf(rintf(v.w * inv), -127.0f), 127.0f);
        outq[i] = c;
    }
}

// ---------------------------------------------------------------------------
// K2: convert ternary weights f32 {-1,0,1} -> int8
// ---------------------------------------------------------------------------
__global__ __launch_bounds__(256) void quant_w_kernel(const float* __restrict__ w) {
    const size_t i = (size_t)blockIdx.x * 256 + threadIdx.x;   // over K*O/4
    const float4 v = reinterpret_cast<const float4*>(w)[i];
    char4 c;
    c.x = (signed char)(int)v.x;
    c.y = (signed char)(int)v.y;
    c.z = (signed char)(int)v.z;
    c.w = (signed char)(int)v.w;
    reinterpret_cast<char4*>(g_wq)[i] = c;
}

// ---------------------------------------------------------------------------
// K3: int8 GEMM, C[T, O] = xq[T, K] @ wq[O, K]^T (both K-major -> mma row.col)
// ---------------------------------------------------------------------------
__device__ __forceinline__ void cp_async16(uint32_t dst, const void* src) {
    asm volatile("cp.async.cg.shared.global [%0], [%1], 16;\n" :: "r"(dst), "l"(src));
}
__device__ __forceinline__ void cp_commit() {
    asm volatile("cp.async.commit_group;\n" ::: "memory");
}
template <int N>
__device__ __forceinline__ void cp_wait() {
    asm volatile("cp.async.wait_group %0;\n" :: "n"(N) : "memory");
}

__global__ __launch_bounds__(256, 1)
void gemm_kernel(const float* __restrict__ wscale_p,
                 const float* __restrict__ bias,
                 float* __restrict__ out) {
    __shared__ int8_t As[2][BM * ASTRIDE];
    __shared__ int8_t Bs[2][BN * ASTRIDE];

    const int tid  = threadIdx.x;
    const int bm   = blockIdx.y;     // M tile (64)
    const int bn   = blockIdx.x;     // N tile (32)
    const int warp = tid >> 5;
    const int lane = tid & 31;
    const int wm   = warp & 3;       // 0..3 -> 32 rows each
    const int wn   = warp >> 2;      // 0..1 -> 64 cols each

    const int8_t* Ag = g_xq + (size_t)bm * BM * KDIM;
    const int8_t* Bg = g_wq + (size_t)bn * BN * KDIM;

    const uint32_t sA = (uint32_t)__cvta_generic_to_shared(&As[0][0]);
    const uint32_t sB = (uint32_t)__cvta_generic_to_shared(&Bs[0][0]);

    // tile load: 128 rows x 64B = 512 segments of 16B; each thread does 2 per tile
    auto load_tile = [&](int st, int kt) {
        const int kbase = kt * BK;
        #pragma unroll
        for (int rep = 0; rep < 2; rep++) {
            const int s   = tid + rep * 256;
            const int row = s >> 2;
            const int c16 = (s & 3) << 4;
            cp_async16(sA + st * (BM * ASTRIDE) + row * ASTRIDE + c16,
                       Ag + (size_t)row * KDIM + kbase + c16);
            cp_async16(sB + st * (BN * ASTRIDE) + row * ASTRIDE + c16,
                       Bg + (size_t)row * KDIM + kbase + c16);
        }
    };

    int acc[2][8][4] = {};

    constexpr int KT = KDIM / BK;    // 64
    load_tile(0, 0);
    cp_commit();

    for (int kt = 0; kt < KT; kt++) {
        if (kt + 1 < KT) { load_tile((kt + 1) & 1, kt + 1); cp_commit(); cp_wait<1>(); }
        else             { cp_wait<0>(); }
        __syncthreads();

        const int buf = kt & 1;
        const int8_t* Ab = &As[buf][0];
        const int8_t* Bb = &Bs[buf][0];

        #pragma unroll
        for (int ks = 0; ks < 2; ks++) {
            const int kb = ks * 32;
            uint32_t a[2][4], b[8][2];
            #pragma unroll
            for (int mi = 0; mi < 2; mi++) {
                const int r = wm * 32 + mi * 16 + (lane >> 2);
                const int8_t* base = Ab + r * ASTRIDE + kb + (lane & 3) * 4;
                a[mi][0] = *reinterpret_cast<const uint32_t*>(base);
                a[mi][1] = *reinterpret_cast<const uint32_t*>(base + 8 * ASTRIDE);
                a[mi][2] = *reinterpret_cast<const uint32_t*>(base + 16);
                a[mi][3] = *reinterpret_cast<const uint32_t*>(base + 8 * ASTRIDE + 16);
            }
            #pragma unroll
            for (int ni = 0; ni < 8; ni++) {
                const int c = wn * 64 + ni * 8 + (lane >> 2);
                const int8_t* base = Bb + c * ASTRIDE + kb + (lane & 3) * 4;
                b[ni][0] = *reinterpret_cast<const uint32_t*>(base);
                b[ni][1] = *reinterpret_cast<const uint32_t*>(base + 16);
            }
            #pragma unroll
            for (int mi = 0; mi < 2; mi++) {
                #pragma unroll
                for (int ni = 0; ni < 8; ni++) {
                    asm volatile(
                        "mma.sync.aligned.m16n8k32.row.col.s32.s8.s8.s32 "
                        "{%0,%1,%2,%3}, {%4,%5,%6,%7}, {%8,%9}, {%0,%1,%2,%3};\n"
                        : "+r"(acc[mi][ni][0]), "+r"(acc[mi][ni][1]),
                          "+r"(acc[mi][ni][2]), "+r"(acc[mi][ni][3])
                        : "r"(a[mi][0]), "r"(a[mi][1]), "r"(a[mi][2]), "r"(a[mi][3]),
                          "r"(b[ni][0]), "r"(b[ni][1]));
                }
            }
        }
        __syncthreads();
    }

    // epilogue: y = acc * act_scale[row] * w_scale + bias[col]
    const float ws = __ldg(wscale_p);
    #pragma unroll
    for (int mi = 0; mi < 2; mi++) {
        const int r0 = bm * BM + wm * 32 + mi * 16 + (lane >> 2);
        const float s0 = g_ascale[r0] * ws;
        const float s1 = g_ascale[r0 + 8] * ws;
        #pragma unroll
        for (int ni = 0; ni < 8; ni++) {
            const int c = bn * BN + wn * 64 + ni * 8 + (lane & 3) * 2;
            const float b0 = __ldg(bias + c);
            const float b1 = __ldg(bias + c + 1);
            float2 v0 = make_float2((float)acc[mi][ni][0] * s0 + b0,
                                    (float)acc[mi][ni][1] * s0 + b1);
            float2 v1 = make_float2((float)acc[mi][ni][2] * s1 + b0,
                                    (float)acc[mi][ni][3] * s1 + b1);
            *reinterpret_cast<float2*>(out + (size_t)r0 * ODIM + c)       = v0;
            *reinterpret_cast<float2*>(out + (size_t)(r0 + 8) * ODIM + c) = v1;
        }
    }
}

// ---------------------------------------------------------------------------
extern "C" void kernel_launch(void* const* d_in, const int* in_sizes, int n_in,
                              void* d_out, int out_size) {
    const float* x      = (const float*)d_in[0];   // [8192, 4096]
    const float* w_t    = (const float*)d_in[1];   // [4096, 4096]
    const float* wscale = (const float*)d_in[2];   // scalar
    const float* bias   = (const float*)d_in[3];   // [4096]
    float* out          = (float*)d_out;           // [8192, 4096]

    quant_x_kernel<<<T_TOKENS, 256>>>(x);
    quant_w_kernel<<<(int)(((size_t)ODIM * KDIM / 4) / 256), 256>>>(w_t);

    dim3 grid(ODIM / BN, T_TOKENS / BM);   // (32, 64)
    gemm_kernel<<<grid, 256>>>(wscale, bias, out);
}

// round 3
// speedup vs baseline: 1.3870x; 1.3870x over previous
#include <cuda_runtime.h>
#include <cstdint>

// ---------------------------------------------------------------------------
// TernaryLinear, legacy-IMMA path (harness compiles for plain sm_100: no tcgen05).
//   K1: per-row absmax int8 quant of x -> g_xq, g_ascale
//   K2: f32 {-1,0,1} -> int8 weights   -> g_wq
//   K3: int8 GEMM via mma.sync.m16n8k32, ldmatrix.x4 fragment loads,
//       XOR-swizzled smem, 4-stage cp.async pipeline, 2 CTAs/SM.
// ---------------------------------------------------------------------------

#define T_TOKENS 8192
#define KDIM     4096
#define ODIM     4096

#define BM 128
#define BN 128
#define BK 64              // bytes (= int8 elems) per k-tile
#define NSTAGE 4
#define KT (KDIM / BK)     // 64
#define A_BYTES (BM * BK)  // 8 KB
#define B_BYTES (BN * BK)  // 8 KB
#define STAGE_BYTES (A_BYTES + B_BYTES)    // 16 KB
#define DYN_SMEM (NSTAGE * STAGE_BYTES + 128)

__device__ __align__(128) int8_t g_xq[(size_t)T_TOKENS * KDIM];
__device__ __align__(128) int8_t g_wq[(size_t)ODIM * KDIM];
__device__ float g_ascale[T_TOKENS];

// --------------------------- helpers ---------------------------------------
__device__ __forceinline__ uint32_t cvta_s(const void* p) {
    return (uint32_t)__cvta_generic_to_shared(p);
}
__device__ __forceinline__ void cp_async16(uint32_t d, const void* s) {
    asm volatile("cp.async.cg.shared.global [%0], [%1], 16;\n" :: "r"(d), "l"(s));
}
__device__ __forceinline__ void cp_commit() {
    asm volatile("cp.async.commit_group;\n" ::: "memory");
}
template <int N> __device__ __forceinline__ void cp_wait() {
    asm volatile("cp.async.wait_group %0;\n" :: "n"(N) : "memory");
}
__device__ __forceinline__ void ldsm_x4(uint32_t* r, uint32_t addr) {
    asm volatile("ldmatrix.sync.aligned.m8n8.x4.shared.b16 {%0,%1,%2,%3}, [%4];"
                 : "=r"(r[0]), "=r"(r[1]), "=r"(r[2]), "=r"(r[3]) : "r"(addr));
}
__device__ __forceinline__ void mma16832(int* d, const uint32_t* a,
                                         uint32_t b0, uint32_t b1) {
    asm volatile(
        "mma.sync.aligned.m16n8k32.row.col.s32.s8.s8.s32 "
        "{%0,%1,%2,%3}, {%4,%5,%6,%7}, {%8,%9}, {%0,%1,%2,%3};\n"
        : "+r"(d[0]), "+r"(d[1]), "+r"(d[2]), "+r"(d[3])
        : "r"(a[0]), "r"(a[1]), "r"(a[2]), "r"(a[3]), "r"(b0), "r"(b1));
}

// ---------------------------------------------------------------------------
// K1: quantize activations (30us, near DRAM-bound; unchanged)
// ---------------------------------------------------------------------------
__global__ __launch_bounds__(256) void quant_x_kernel(const float* __restrict__ x) {
    const int row = blockIdx.x;
    const float4* xr = reinterpret_cast<const float4*>(x + (size_t)row * KDIM);

    float m = 0.0f;
    #pragma unroll 4
    for (int i = threadIdx.x; i < KDIM / 4; i += 256) {
        float4 v = xr[i];
        m = fmaxf(m, fmaxf(fmaxf(fabsf(v.x), fabsf(v.y)),
                           fmaxf(fabsf(v.z), fabsf(v.w))));
    }
    #pragma unroll
    for (int o = 16; o; o >>= 1) m = fmaxf(m, __shfl_xor_sync(0xffffffffu, m, o));

    __shared__ float warpmax[8];
    __shared__ float s_inv;
    const int wid = threadIdx.x >> 5, lane = threadIdx.x & 31;
    if (lane == 0) warpmax[wid] = m;
    __syncthreads();
    if (threadIdx.x == 0) {
        float mm = warpmax[0];
        #pragma unroll
        for (int i = 1; i < 8; i++) mm = fmaxf(mm, warpmax[i]);
        float sc = fmaxf(mm, 1e-10f) / 127.0f;
        g_ascale[row] = sc;
        s_inv = 1.0f / sc;
    }
    __syncthreads();
    const float inv = s_inv;

    char4* outq = reinterpret_cast<char4*>(g_xq + (size_t)row * KDIM);
    for (int i = threadIdx.x; i < KDIM / 4; i += 256) {
        float4 v = xr[i];
        char4 c;
        c.x = (signed char)(int)fminf(fmaxf(rintf(v.x * inv), -127.0f), 127.0f);
        c.y = (signed char)(int)fminf(fmaxf(rintf(v.y * inv), -127.0f), 127.0f);
        c.z = (signed char)(int)fminf(fmaxf(rintf(v.z * inv), -127.0f), 127.0f);
        c.w = (signed char)(int)fminf(fmaxf(rintf(v.w * inv), -127.0f), 127.0f);
        outq[i] = c;
    }
}

// ---------------------------------------------------------------------------
// K2: ternary weights f32 -> int8
// ---------------------------------------------------------------------------
__global__ __launch_bounds__(256) void quant_w_kernel(const float* __restrict__ w) {
    const size_t i = (size_t)blockIdx.x * 256 + threadIdx.x;
    const float4 v = reinterpret_cast<const float4*>(w)[i];
    char4 c;
    c.x = (signed char)(int)v.x;
    c.y = (signed char)(int)v.y;
    c.z = (signed char)(int)v.z;
    c.w = (signed char)(int)v.w;
    reinterpret_cast<char4*>(g_wq)[i] = c;
}

// ---------------------------------------------------------------------------
// K3: int8 GEMM. C[T,O] = xq[T,K] @ wq[O,K]^T
// smem layout per stage: A rows then B rows; each row = 64B = 4 chunks of 16B,
// chunk swizzle: phys_chunk = c ^ ((row >> 1) & 3)  (conflict-free STS.128 + LDSM)
// ---------------------------------------------------------------------------
__global__ __launch_bounds__(256, 2)
void gemm_kernel(const float* __restrict__ wscale_p,
                 const float* __restrict__ bias,
                 float* __restrict__ out) {
    extern __shared__ int8_t smem_raw[];
    const uint32_t smem_u = (cvta_s(smem_raw) + 127u) & ~127u;

    const int tid  = threadIdx.x;
    const int lane = tid & 31;
    const int wid  = tid >> 5;
    const int wm   = wid & 3;        // 4 row-groups of 32
    const int wn   = wid >> 2;       // 2 col-groups of 64
    const int bm   = blockIdx.y;     // M tile (64)
    const int bn   = blockIdx.x;     // N tile (32)

    const int8_t* Ag = g_xq + (size_t)bm * BM * KDIM;
    const int8_t* Bg = g_wq + (size_t)bn * BN * KDIM;

    // cp.async chunk assignment: thread t, rep r -> chunk id = t + 256*r
    // row = id>>2, c = id&3
    auto load_tile = [&](int st, int kt) {
        const uint32_t sb = smem_u + st * STAGE_BYTES;
        const int koff = kt * BK;
        #pragma unroll
        for (int r = 0; r < 2; r++) {
            const int id  = tid + (r << 8);
            const int row = id >> 2;
            const int c   = id & 3;
            const uint32_t phys = (uint32_t)((c ^ ((row >> 1) & 3)) << 4);
            cp_async16(sb + row * BK + phys,
                       Ag + (size_t)row * KDIM + koff + (c << 4));
            cp_async16(sb + A_BYTES + row * BK + phys,
                       Bg + (size_t)row * KDIM + koff + (c << 4));
        }
    };

    // Precomputed per-lane ldmatrix offsets (ks=0; ks=1 is ^32).
    // A (x4): matrix m: rows +(m&1)*8, chunk m>>1
    uint32_t a_off[2];
    {
        const int m  = lane >> 3;
        const int rr = ((m & 1) << 3) + (lane & 7);
        const int cb = m >> 1;
        #pragma unroll
        for (int mi = 0; mi < 2; mi++) {
            const int row = wm * 32 + mi * 16 + rr;
            a_off[mi] = (uint32_t)(row * BK + ((cb ^ ((row >> 1) & 3)) << 4));
        }
    }
    // B (x4): matrix m: cols +(m>>1)*8, chunk m&1
    uint32_t b_off[4];
    {
        const int m  = lane >> 3;
        const int cr = ((m >> 1) << 3) + (lane & 7);
        const int cb = m & 1;
        #pragma unroll
        for (int n2 = 0; n2 < 4; n2++) {
            const int col = wn * 64 + n2 * 16 + cr;
            b_off[n2] = (uint32_t)(A_BYTES + col * BK + ((cb ^ ((col >> 1) & 3)) << 4));
        }
    }

    int acc[2][8][4] = {};

    load_tile(0, 0); cp_commit();
    load_tile(1, 1); cp_commit();
    load_tile(2, 2); cp_commit();

    for (int kt = 0; kt < KT; kt++) {
        cp_wait<2>();
        __syncthreads();

        const int nxt = kt + 3;
        if (nxt < KT) load_tile(nxt & (NSTAGE - 1), nxt);
        cp_commit();                          // empty group in tail keeps count

        const uint32_t sb = smem_u + (kt & (NSTAGE - 1)) * STAGE_BYTES;

        #pragma unroll
        for (int ks = 0; ks < 2; ks++) {
            const uint32_t kx = ks << 5;      // XOR advance to chunks 2,3
            uint32_t a[2][4], b[4][4];
            #pragma unroll
            for (int mi = 0; mi < 2; mi++) ldsm_x4(a[mi], sb + (a_off[mi] ^ kx));
            #pragma unroll
            for (int n2 = 0; n2 < 4; n2++)  ldsm_x4(b[n2], sb + (b_off[n2] ^ kx));
            #pragma unroll
            for (int mi = 0; mi < 2; mi++) {
                #pragma unroll
                for (int ni = 0; ni < 8; ni++) {
                    const uint32_t* bb = b[ni >> 1];
                    const int o = (ni & 1) << 1;
                    mma16832(acc[mi][ni], a[mi], bb[o], bb[o + 1]);
                }
            }
        }
    }

    // epilogue: y = acc * act_scale[row] * w_scale + bias[col]
    const float ws = __ldg(wscale_p);
    #pragma unroll
    for (int mi = 0; mi < 2; mi++) {
        const int r0 = bm * BM + wm * 32 + mi * 16 + (lane >> 2);
        const float s0 = g_ascale[r0] * ws;
        const float s1 = g_ascale[r0 + 8] * ws;
        #pragma unroll
        for (int ni = 0; ni < 8; ni++) {
            const int c = bn * BN + wn * 64 + ni * 8 + ((lane & 3) << 1);
            const float b0 = __ldg(bias + c);
            const float b1 = __ldg(bias + c + 1);
            float2 v0 = make_float2((float)acc[mi][ni][0] * s0 + b0,
                                    (float)acc[mi][ni][1] * s0 + b1);
            float2 v1 = make_float2((float)acc[mi][ni][2] * s1 + b0,
                                    (float)acc[mi][ni][3] * s1 + b1);
            *reinterpret_cast<float2*>(out + (size_t)r0 * ODIM + c)       = v0;
            *reinterpret_cast<float2*>(out + (size_t)(r0 + 8) * ODIM + c) = v1;
        }
    }
}

// ---------------------------------------------------------------------------
extern "C" void kernel_launch(void* const* d_in, const int* in_sizes, int n_in,
                              void* d_out, int out_size) {
    const float* x      = (const float*)d_in[0];   // [8192, 4096]
    const float* w_t    = (const float*)d_in[1];   // [4096, 4096]
    const float* wscale = (const float*)d_in[2];   // scalar
    const float* bias   = (const float*)d_in[3];   // [4096]
    float* out          = (float*)d_out;           // [8192, 4096]

    quant_x_kernel<<<T_TOKENS, 256>>>(x);
    quant_w_kernel<<<(int)(((size_t)ODIM * KDIM / 4) / 256), 256>>>(w_t);

    cudaFuncSetAttribute(gemm_kernel, cudaFuncAttributeMaxDynamicSharedMemorySize,
                         DYN_SMEM);
    dim3 grid(ODIM / BN, T_TOKENS / BM);   // (32, 64)
    gemm_kernel<<<grid, 256, DYN_SMEM>>>(wscale, bias, out);
}

// round 4
// speedup vs baseline: 1.6611x; 1.1976x over previous
#include <cuda_runtime.h>
#include <cstdint>

// ---------------------------------------------------------------------------
// TernaryLinear, legacy-IMMA path (harness targets plain sm_100: no tcgen05).
//   K1: per-row absmax int8 quant of x (single-pass, register-cached row)
//   K2: f32 {-1,0,1} -> int8 weights
//   K3: int8 GEMM mma.sync.m16n8k32, 4 warps @ 64x64 warp tile (low smem
//       duplication), ldmatrix.x4, XOR swizzle, 4-stage cp.async, 2 CTA/SM.
// ---------------------------------------------------------------------------

#define T_TOKENS 8192
#define KDIM     4096
#define ODIM     4096

#define BM 128
#define BN 128
#define BK 64              // int8 elems per k-tile
#define NSTAGE 4
#define KT (KDIM / BK)     // 64
#define A_BYTES (BM * BK)  // 8 KB
#define B_BYTES (BN * BK)  // 8 KB
#define STAGE_BYTES (A_BYTES + B_BYTES)    // 16 KB
#define DYN_SMEM (NSTAGE * STAGE_BYTES + 128)

__device__ __align__(128) int8_t g_xq[(size_t)T_TOKENS * KDIM];
__device__ __align__(128) int8_t g_wq[(size_t)ODIM * KDIM];
__device__ float g_ascale[T_TOKENS];

// --------------------------- helpers ---------------------------------------
__device__ __forceinline__ uint32_t cvta_s(const void* p) {
    return (uint32_t)__cvta_generic_to_shared(p);
}
__device__ __forceinline__ void cp_async16(uint32_t d, const void* s) {
    asm volatile("cp.async.cg.shared.global [%0], [%1], 16;\n" :: "r"(d), "l"(s));
}
__device__ __forceinline__ void cp_commit() {
    asm volatile("cp.async.commit_group;\n" ::: "memory");
}
template <int N> __device__ __forceinline__ void cp_wait() {
    asm volatile("cp.async.wait_group %0;\n" :: "n"(N) : "memory");
}
__device__ __forceinline__ void ldsm_x4(uint32_t* r, uint32_t addr) {
    asm volatile("ldmatrix.sync.aligned.m8n8.x4.shared.b16 {%0,%1,%2,%3}, [%4];"
                 : "=r"(r[0]), "=r"(r[1]), "=r"(r[2]), "=r"(r[3]) : "r"(addr));
}
__device__ __forceinline__ void mma16832(int* d, const uint32_t* a,
                                         uint32_t b0, uint32_t b1) {
    asm volatile(
        "mma.sync.aligned.m16n8k32.row.col.s32.s8.s8.s32 "
        "{%0,%1,%2,%3}, {%4,%5,%6,%7}, {%8,%9}, {%0,%1,%2,%3};\n"
        : "+r"(d[0]), "+r"(d[1]), "+r"(d[2]), "+r"(d[3])
        : "r"(a[0]), "r"(a[1]), "r"(a[2]), "r"(a[3]), "r"(b0), "r"(b1));
}

// ---------------------------------------------------------------------------
// K1: quantize activations. Single global read: row cached in registers.
// ---------------------------------------------------------------------------
__global__ __launch_bounds__(256) void quant_x_kernel(const float* __restrict__ x) {
    const int row = blockIdx.x;
    const float4* xr = reinterpret_cast<const float4*>(x + (size_t)row * KDIM);

    float4 v[4];
    float m = 0.0f;
    #pragma unroll
    for (int i = 0; i < 4; i++) {
        v[i] = xr[threadIdx.x + (i << 8)];
        m = fmaxf(m, fmaxf(fmaxf(fabsf(v[i].x), fabsf(v[i].y)),
                           fmaxf(fabsf(v[i].z), fabsf(v[i].w))));
    }
    #pragma unroll
    for (int o = 16; o; o >>= 1) m = fmaxf(m, __shfl_xor_sync(0xffffffffu, m, o));

    __shared__ float warpmax[8];
    __shared__ float s_inv;
    const int wid = threadIdx.x >> 5, lane = threadIdx.x & 31;
    if (lane == 0) warpmax[wid] = m;
    __syncthreads();
    if (threadIdx.x == 0) {
        float mm = warpmax[0];
        #pragma unroll
        for (int i = 1; i < 8; i++) mm = fmaxf(mm, warpmax[i]);
        float sc = fmaxf(mm, 1e-10f) / 127.0f;
        g_ascale[row] = sc;
        s_inv = 1.0f / sc;
    }
    __syncthreads();
    const float inv = s_inv;

    char4* outq = reinterpret_cast<char4*>(g_xq + (size_t)row * KDIM);
    #pragma unroll
    for (int i = 0; i < 4; i++) {
        char4 c;
        c.x = (signed char)(int)fminf(fmaxf(rintf(v[i].x * inv), -127.0f), 127.0f);
        c.y = (signed char)(int)fminf(fmaxf(rintf(v[i].y * inv), -127.0f), 127.0f);
        c.z = (signed char)(int)fminf(fmaxf(rintf(v[i].z * inv), -127.0f), 127.0f);
        c.w = (signed char)(int)fminf(fmaxf(rintf(v[i].w * inv), -127.0f), 127.0f);
        outq[threadIdx.x + (i << 8)] = c;
    }
}

// ---------------------------------------------------------------------------
// K2: ternary weights f32 -> int8
// ---------------------------------------------------------------------------
__global__ __launch_bounds__(256) void quant_w_kernel(const float* __restrict__ w) {
    const size_t i = (size_t)blockIdx.x * 256 + threadIdx.x;
    const float4 v = reinterpret_cast<const float4*>(w)[i];
    char4 c;
    c.x = (signed char)(int)v.x;
    c.y = (signed char)(int)v.y;
    c.z = (signed char)(int)v.z;
    c.w = (signed char)(int)v.w;
    reinterpret_cast<char4*>(g_wq)[i] = c;
}

// ---------------------------------------------------------------------------
// K3: int8 GEMM. C[T,O] = xq[T,K] @ wq[O,K]^T
// 4 warps, warp tile 64x64. smem: rows of 64B = 4 chunks of 16B,
// chunk swizzle: phys = c ^ ((row >> 1) & 3)
// ---------------------------------------------------------------------------
__global__ __launch_bounds__(128, 2)
void gemm_kernel(const float* __restrict__ wscale_p,
                 const float* __restrict__ bias,
                 float* __restrict__ out) {
    extern __shared__ int8_t smem_raw[];
    const uint32_t smem_u = (cvta_s(smem_raw) + 127u) & ~127u;

    const int tid  = threadIdx.x;
    const int lane = tid & 31;
    const int wid  = tid >> 5;
    const int wm   = wid & 1;        // 2 row-groups of 64
    const int wn   = wid >> 1;       // 2 col-groups of 64
    const int bm   = blockIdx.y;
    const int bn   = blockIdx.x;

    const int8_t* Ag = g_xq + (size_t)bm * BM * KDIM;
    const int8_t* Bg = g_wq + (size_t)bn * BN * KDIM;

    // 1024 chunks/tile, 128 threads -> 8 chunks each (4 A + 4 B)
    auto load_tile = [&](int st, int kt) {
        const uint32_t sb = smem_u + st * STAGE_BYTES;
        const int koff = kt * BK;
        #pragma unroll
        for (int r = 0; r < 4; r++) {
            const int id  = tid + (r << 7);
            const int row = id >> 2;
            const int c   = id & 3;
            const uint32_t phys = (uint32_t)((c ^ ((row >> 1) & 3)) << 4);
            cp_async16(sb + row * BK + phys,
                       Ag + (size_t)row * KDIM + koff + (c << 4));
            cp_async16(sb + A_BYTES + row * BK + phys,
                       Bg + (size_t)row * KDIM + koff + (c << 4));
        }
    };

    // ldmatrix offsets (ks=0; ks=1 via ^32)
    uint32_t a_off[4];
    {
        const int m  = lane >> 3;
        const int rr = ((m & 1) << 3) + (lane & 7);
        const int cb = m >> 1;
        #pragma unroll
        for (int mi = 0; mi < 4; mi++) {
            const int row = wm * 64 + mi * 16 + rr;
            a_off[mi] = (uint32_t)(row * BK + ((cb ^ ((row >> 1) & 3)) << 4));
        }
    }
    uint32_t b_off[4];
    {
        const int m  = lane >> 3;
        const int cr = ((m >> 1) << 3) + (lane & 7);
        const int cb = m & 1;
        #pragma unroll
        for (int n2 = 0; n2 < 4; n2++) {
            const int col = wn * 64 + n2 * 16 + cr;
            b_off[n2] = (uint32_t)(A_BYTES + col * BK + ((cb ^ ((col >> 1) & 3)) << 4));
        }
    }

    int acc[4][8][4] = {};

    load_tile(0, 0); cp_commit();
    load_tile(1, 1); cp_commit();
    load_tile(2, 2); cp_commit();

    for (int kt = 0; kt < KT; kt++) {
        cp_wait<2>();
        __syncthreads();

        const int nxt = kt + 3;
        if (nxt < KT) load_tile(nxt & (NSTAGE - 1), nxt);
        cp_commit();

        const uint32_t sb = smem_u + (kt & (NSTAGE - 1)) * STAGE_BYTES;

        #pragma unroll
        for (int ks = 0; ks < 2; ks++) {
            const uint32_t kx = ks << 5;
            uint32_t a[4][4], b[4][4];
            #pragma unroll
            for (int mi = 0; mi < 4; mi++) ldsm_x4(a[mi], sb + (a_off[mi] ^ kx));
            #pragma unroll
            for (int n2 = 0; n2 < 4; n2++)  ldsm_x4(b[n2], sb + (b_off[n2] ^ kx));
            #pragma unroll
            for (int mi = 0; mi < 4; mi++) {
                #pragma unroll
                for (int ni = 0; ni < 8; ni++) {
                    const uint32_t* bb = b[ni >> 1];
                    const int o = (ni & 1) << 1;
                    mma16832(acc[mi][ni], a[mi], bb[o], bb[o + 1]);
                }
            }
        }
    }

    // epilogue
    const float ws = __ldg(wscale_p);
    #pragma unroll
    for (int mi = 0; mi < 4; mi++) {
        const int r0 = bm * BM + wm * 64 + mi * 16 + (lane >> 2);
        const float s0 = g_ascale[r0] * ws;
        const float s1 = g_ascale[r0 + 8] * ws;
        #pragma unroll
        for (int ni = 0; ni < 8; ni++) {
            const int c = bn * BN + wn * 64 + ni * 8 + ((lane & 3) << 1);
            const float b0 = __ldg(bias + c);
            const float b1 = __ldg(bias + c + 1);
            float2 v0 = make_float2((float)acc[mi][ni][0] * s0 + b0,
                                    (float)acc[mi][ni][1] * s0 + b1);
            float2 v1 = make_float2((float)acc[mi][ni][2] * s1 + b0,
                                    (float)acc[mi][ni][3] * s1 + b1);
            *reinterpret_cast<float2*>(out + (size_t)r0 * ODIM + c)       = v0;
            *reinterpret_cast<float2*>(out + (size_t)(r0 + 8) * ODIM + c) = v1;
        }
    }
}

// ---------------------------------------------------------------------------
extern "C" void kernel_launch(void* const* d_in, const int* in_sizes, int n_in,
                              void* d_out, int out_size) {
    const float* x      = (const float*)d_in[0];   // [8192, 4096]
    const float* w_t    = (const float*)d_in[1];   // [4096, 4096]
    const float* wscale = (const float*)d_in[2];   // scalar
    const float* bias   = (const float*)d_in[3];   // [4096]
    float* out          = (float*)d_out;           // [8192, 4096]

    quant_x_kernel<<<T_TOKENS, 256>>>(x);
    quant_w_kernel<<<(int)(((size_t)ODIM * KDIM / 4) / 256), 256>>>(w_t);

    cudaFuncSetAttribute(gemm_kernel, cudaFuncAttributeMaxDynamicSharedMemorySize,
                         DYN_SMEM);
    dim3 grid(ODIM / BN, T_TOKENS / BM);   // (32, 64)
    gemm_kernel<<<grid, 128, DYN_SMEM>>>(wscale, bias, out);
}